// round 11
// baseline (speedup 1.0000x reference)
#include <cuda_runtime.h>
#include <cuda_bf16.h>
#include <cuda_fp8.h>
#include <cstdint>

#define MDIM 16384
#define KDIM 2048
#define NDIM 2048
#define KB   (KDIM / 128)   // 16 quant blocks along K

// Scratch: fp8 operands + per-block float scales for activations.
__device__ uint8_t g_x8[(size_t)MDIM * KDIM];   // 32 MiB
__device__ uint8_t g_w8[(size_t)NDIM * KDIM];   // 4 MiB
__device__ float   g_sa[(size_t)MDIM * KB];     // 1 MiB

__device__ __forceinline__ float bf16_round(float f) {
    return __bfloat162float(__float2bfloat16(f));
}

// ---------------------------------------------------------------------------
// Fused quantization kernel (unchanged: measured ~26us combined).
// ---------------------------------------------------------------------------
constexpr int XBLOCKS = MDIM * KB;            // 262144 quant blocks
constexpr int XCTAS   = XBLOCKS / (8 * 4);    // 8192
constexpr int WCTAS   = 1024;

__global__ void quant_fused_kernel(const float* __restrict__ x,
                                   const float* __restrict__ w) {
    const int cta = blockIdx.x;
    if (cta < XCTAS) {
        const int warp = cta * 8 + (threadIdx.x >> 5);
        const int lane = threadIdx.x & 31;
        const size_t b0 = (size_t)warp * 4;

        float4 v4[4];
#pragma unroll
        for (int j = 0; j < 4; j++)
            v4[j] = ((const float4*)x)[(b0 + j) * 32 + lane];

        float v[4][4], amax[4];
#pragma unroll
        for (int j = 0; j < 4; j++) {
            v[j][0] = bf16_round(v4[j].x);
            v[j][1] = bf16_round(v4[j].y);
            v[j][2] = bf16_round(v4[j].z);
            v[j][3] = bf16_round(v4[j].w);
            amax[j] = fmaxf(fmaxf(fabsf(v[j][0]), fabsf(v[j][1])),
                            fmaxf(fabsf(v[j][2]), fabsf(v[j][3])));
        }
#pragma unroll
        for (int o = 16; o; o >>= 1) {
#pragma unroll
            for (int j = 0; j < 4; j++)
                amax[j] = fmaxf(amax[j], __shfl_xor_sync(0xffffffffu, amax[j], o));
        }
#pragma unroll
        for (int j = 0; j < 4; j++) {
            float s = fmaxf(amax[j], 1e-4f) / 448.0f;
            int e; float m = frexpf(s, &e);
            float s2 = (m == 0.5f) ? ldexpf(1.f, e - 1) : ldexpf(1.f, e);
            float inv = 1.f / s2;
            __nv_fp8x2_storage_t lo = __nv_cvt_float2_to_fp8x2(
                make_float2(v[j][0] * inv, v[j][1] * inv), __NV_SATFINITE, __NV_E4M3);
            __nv_fp8x2_storage_t hi = __nv_cvt_float2_to_fp8x2(
                make_float2(v[j][2] * inv, v[j][3] * inv), __NV_SATFINITE, __NV_E4M3);
            ((uint32_t*)g_x8)[(b0 + j) * 32 + lane] = (uint32_t)lo | ((uint32_t)hi << 16);
            if (lane == 0) g_sa[b0 + j] = s2;
        }
    } else {
        const int t = (cta - XCTAS) * 256 + threadIdx.x;
#pragma unroll
        for (int j = 0; j < 4; j++) {
            int i = t + j * (WCTAS * 256);
            float4 w4 = ((const float4*)w)[i];
            __nv_fp8x2_storage_t lo = __nv_cvt_float2_to_fp8x2(
                make_float2(w4.x, w4.y), __NV_SATFINITE, __NV_E4M3);
            __nv_fp8x2_storage_t hi = __nv_cvt_float2_to_fp8x2(
                make_float2(w4.z, w4.w), __NV_SATFINITE, __NV_E4M3);
            ((uint32_t*)g_w8)[i] = (uint32_t)lo | ((uint32_t)hi << 16);
        }
    }
}

// ---------------------------------------------------------------------------
// FP8 NT GEMM: CTA 64x64, 256 thr, 8 warps (4m x 2n), warp tile 16x32.
// SINGLE accumulator with running rescale: acc *= f[kb-1]/f[kb] (exact for
// pow2 activation scales), mma accumulates directly -> no `part` array,
// no per-block zeroing. Target 64 regs -> 4 CTAs/SM (32 warps, 8/SMSP).
// 3-stage cp.async ring (55.3KB smem/CTA -> 221KB for 4 CTAs).
// ---------------------------------------------------------------------------
constexpr int BM = 64, BN = 64;
constexpr int STAGES = 3;
constexpr int ROWB = 128 + 16;                       // 144 B/row, conflict-free
constexpr int STAGE_BYTES = (BM + BN) * ROWB;        // 18432
constexpr int SMEM_TOTAL = STAGES * STAGE_BYTES;     // 55296

__device__ __forceinline__ void cp_async16(uint32_t dst, const void* src) {
    asm volatile("cp.async.cg.shared.global [%0], [%1], 16;\n" :: "r"(dst), "l"(src));
}
__device__ __forceinline__ void cp_commit() {
    asm volatile("cp.async.commit_group;\n" ::: "memory");
}
template <int N>
__device__ __forceinline__ void cp_wait() {
    asm volatile("cp.async.wait_group %0;\n" :: "n"(N) : "memory");
}
__device__ __forceinline__ void ldm_x4(uint32_t& r0, uint32_t& r1, uint32_t& r2, uint32_t& r3,
                                       uint32_t addr) {
    asm volatile("ldmatrix.sync.aligned.m8n8.x4.shared.b16 {%0,%1,%2,%3}, [%4];\n"
                 : "=r"(r0), "=r"(r1), "=r"(r2), "=r"(r3) : "r"(addr));
}
__device__ __forceinline__ void mma_fp8(float* c, const uint32_t* a, const uint32_t* b) {
    asm volatile("mma.sync.aligned.m16n8k32.row.col.f32.e4m3.e4m3.f32 "
                 "{%0,%1,%2,%3}, {%4,%5,%6,%7}, {%8,%9}, {%0,%1,%2,%3};\n"
                 : "+f"(c[0]), "+f"(c[1]), "+f"(c[2]), "+f"(c[3])
                 : "r"(a[0]), "r"(a[1]), "r"(a[2]), "r"(a[3]), "r"(b[0]), "r"(b[1]));
}

__global__ __launch_bounds__(256, 4) void gemm_kernel(float* __restrict__ C,
                                                      const float* __restrict__ sinv) {
    extern __shared__ uint8_t sm[];
    const int tid = threadIdx.x;
    const int lane = tid & 31;
    const int wid = tid >> 5;                 // 0..7
    const int bm = blockIdx.y * BM;
    const int bn = blockIdx.x * BN;
    const int wm = (wid & 3) * 16;            // 4 m-tiles of 16
    const int wn = (wid >> 2) * 32;           // 2 n-cols of 32

    const uint32_t sm_u32 = (uint32_t)__cvta_generic_to_shared(sm);

    // ---- per-thread loader pointers (2 base ptrs; siblings derived) ----
    // chunks c = tid + 256*i, i=0..3; i<2 -> A (c<512), i>=2 -> B.
    const int rowA = tid >> 3, ccA = tid & 7;           // i=0 row, i=1 = row+32
    const int cB = tid + 512 - 512;                     // B chunk index = tid for i=2
    const int rowB = cB >> 3, ccB = cB & 7;             // i=3 = row+32
    const uint8_t* gA = g_x8 + (size_t)(bm + rowA) * KDIM + ccA * 16;
    const uint8_t* gB = g_w8 + (size_t)(bn + rowB) * KDIM + ccB * 16;
    const uint32_t sA0 = (uint32_t)(rowA * ROWB + ccA * 16);
    const uint32_t sB0 = (uint32_t)(BM * ROWB + rowB * ROWB + ccB * 16);
    constexpr uint32_t ROWSKIP_S = 32u * ROWB;          // +32 rows in smem
    constexpr size_t   ROWSKIP_G = 32u * KDIM;          // +32 rows in gmem

    auto load_stage = [&](int s, int kb) {
        uint32_t base = sm_u32 + (uint32_t)(s * STAGE_BYTES);
        uint32_t koff = (uint32_t)kb << 7;    // kb * 128 bytes
        cp_async16(base + sA0, gA + koff);
        cp_async16(base + sA0 + ROWSKIP_S, gA + ROWSKIP_G + koff);
        cp_async16(base + sB0, gB + koff);
        cp_async16(base + sB0 + ROWSKIP_S, gB + ROWSKIP_G + koff);
    };

    float acc[4][4];
#pragma unroll
    for (int j = 0; j < 4; j++)
#pragma unroll
        for (int l = 0; l < 4; l++) acc[j][l] = 0.f;

    load_stage(0, 0); cp_commit();
    load_stage(1, 1); cp_commit();

    // hoisted ldmatrix address components
    const int la_row  = lane & 15;
    const int la_half = lane >> 4;
    const int lb_row  = ((lane >> 4) << 3) + (lane & 7);
    const int lb_half = (lane >> 3) & 1;
    const uint32_t aBase  = (uint32_t)((wm + la_row) * ROWB + la_half * 16);
    const uint32_t bBase0 = (uint32_t)(BM * ROWB + (wn + lb_row) * ROWB + lb_half * 16);
    const uint32_t bBase1 = bBase0 + 16u * ROWB;
    const int gr = lane >> 2;

    // scale pointers
    const float* psa0 = g_sa + (size_t)(bm + wm + gr) * KB;   // acc rows c0,c1
    const float* psa1 = psa0 + 8 * KB;                        // acc rows c2,c3
    const float* psw  = sinv + (size_t)(bn >> 7) * KB;

    // running-rescale state: fprev = combined scale of previous block
    float fprev0 = __ldg(psa0) * __ldg(psw);
    float fprev1 = __ldg(psa1) * __ldg(psw);

    for (int kb = 0; kb < KB; kb++) {
        int rem = KB - 1 - kb;
        if (rem >= 1) cp_wait<1>(); else cp_wait<0>();
        __syncthreads();
        if (kb + 2 < KB) { load_stage((kb + 2) % STAGES, kb + 2); cp_commit(); }

        // ---- rescale acc into units of this block's scale (exact for pow2) ----
        if (kb > 0) {
            float swk = __ldg(psw + kb);
            float f0 = __ldg(psa0 + kb) * swk;
            float f1 = __ldg(psa1 + kb) * swk;
            float r0 = fprev0 * __frcp_rn(f0);
            float r1 = fprev1 * __frcp_rn(f1);
            fprev0 = f0; fprev1 = f1;
#pragma unroll
            for (int nt = 0; nt < 4; nt++) {
                acc[nt][0] *= r0;
                acc[nt][1] *= r0;
                acc[nt][2] *= r1;
                acc[nt][3] *= r1;
            }
        }

        const uint32_t st = sm_u32 + (uint32_t)((kb % STAGES) * STAGE_BYTES);

#pragma unroll
        for (int ks = 0; ks < 4; ks++) {      // four k32 steps in BK=128
            const uint32_t k0 = (uint32_t)(ks * 32);
            uint32_t a[4];
            ldm_x4(a[0], a[1], a[2], a[3], st + aBase + k0);
            uint32_t b[4];
            ldm_x4(b[0], b[1], b[2], b[3], st + bBase0 + k0);
            mma_fp8(acc[0], a, b + 0);
            mma_fp8(acc[1], a, b + 2);
            ldm_x4(b[0], b[1], b[2], b[3], st + bBase1 + k0);
            mma_fp8(acc[2], a, b + 0);
            mma_fp8(acc[3], a, b + 2);
        }
    }

    // ---- epilogue: apply final block scale, round to bf16, store fp32 ----
    const int gid = lane >> 2, tig = lane & 3;
#pragma unroll
    for (int nt = 0; nt < 4; nt++) {
        int row = bm + wm + gid;
        int col = bn + wn + nt * 8 + tig * 2;
        float2 v01 = make_float2(bf16_round(acc[nt][0] * fprev0),
                                 bf16_round(acc[nt][1] * fprev0));
        *(float2*)&C[(size_t)row * NDIM + col] = v01;
        float2 v23 = make_float2(bf16_round(acc[nt][2] * fprev1),
                                 bf16_round(acc[nt][3] * fprev1));
        *(float2*)&C[(size_t)(row + 8) * NDIM + col] = v23;
    }
}

// ---------------------------------------------------------------------------
// Inputs identified BY ELEMENT COUNT: x 33554432, weight 4194304, sinv 256.
// ---------------------------------------------------------------------------
extern "C" void kernel_launch(void* const* d_in, const int* in_sizes, int n_in,
                              void* d_out, int out_size) {
    const float* x = nullptr; const float* w = nullptr; const float* sinv = nullptr;
    for (int i = 0; i < n_in; i++) {
        long long sz = in_sizes[i];
        if (sz == (long long)MDIM * KDIM)      x    = (const float*)d_in[i];
        else if (sz == (long long)NDIM * KDIM) w    = (const float*)d_in[i];
        else                                   sinv = (const float*)d_in[i];
    }
    if (!x)    x    = (const float*)d_in[0];
    if (!w)    w    = (const float*)d_in[1];
    if (!sinv) sinv = (const float*)d_in[2];
    float* out = (float*)d_out;

    // 1) fused quantization (x + w in one launch)
    quant_fused_kernel<<<XCTAS + WCTAS, 256>>>(x, w);

    // 2) fp8 GEMM, running-rescale accumulation, 4 CTAs/SM target
    cudaFuncSetAttribute(gemm_kernel, cudaFuncAttributeMaxDynamicSharedMemorySize, SMEM_TOTAL);
    dim3 grid(NDIM / BN, MDIM / BM);               // (32, 256)
    gemm_kernel<<<grid, 256, SMEM_TOTAL>>>(out, sinv);
}

// round 12
// speedup vs baseline: 1.0468x; 1.0468x over previous
#include <cuda_runtime.h>
#include <cuda_bf16.h>
#include <cuda_fp8.h>
#include <cstdint>

#define MDIM 16384
#define KDIM 2048
#define NDIM 2048
#define KB   (KDIM / 128)   // 16 quant blocks along K

// Scratch: fp8 operands + per-block float scales for activations.
__device__ uint8_t g_x8[(size_t)MDIM * KDIM];   // 32 MiB
__device__ uint8_t g_w8[(size_t)NDIM * KDIM];   // 4 MiB
__device__ float   g_sa[(size_t)MDIM * KB];     // 1 MiB

__device__ __forceinline__ float bf16_round(float f) {
    return __bfloat162float(__float2bfloat16(f));
}

// ---------------------------------------------------------------------------
// Fused quantization kernel, v2.
//  x part: 8 lanes per 128-block (lane owns 16 consecutive elems):
//    4x float4 loads (MLP=4), 3-step shfl reduction, ONE 16B store per lane.
//  w part: 4 consecutive float4 reads -> one uint4 (16B) store.
// ---------------------------------------------------------------------------
constexpr int XBLOCKS = MDIM * KB;            // 262144 quant blocks
constexpr int XCTAS   = XBLOCKS / 32;         // 8192 (32 blocks per 256-thr CTA)
constexpr int WCTAS   = 1024;                 // 262144 threads x 4 float4

__global__ void quant_fused_kernel(const float* __restrict__ x,
                                   const float* __restrict__ w) {
    const int cta = blockIdx.x;
    if (cta < XCTAS) {
        const int warp = (threadIdx.x >> 5);
        const int lane = threadIdx.x & 31;
        const int j = lane >> 3;                       // block within warp's 4
        const int r = lane & 7;                        // 16-elem slice within block
        const size_t b = (size_t)cta * 32 + warp * 4 + j;

        const float4* px = (const float4*)(x + b * 128 + r * 16);
        float4 f4[4];
#pragma unroll
        for (int i = 0; i < 4; i++) f4[i] = px[i];

        float v[16];
        float amax = 0.f;
#pragma unroll
        for (int i = 0; i < 4; i++) {
            v[4 * i + 0] = bf16_round(f4[i].x);
            v[4 * i + 1] = bf16_round(f4[i].y);
            v[4 * i + 2] = bf16_round(f4[i].z);
            v[4 * i + 3] = bf16_round(f4[i].w);
#pragma unroll
            for (int q = 0; q < 4; q++)
                amax = fmaxf(amax, fabsf(v[4 * i + q]));
        }
        // reduce across the 8 lanes of this block (groups are xor-aligned)
#pragma unroll
        for (int o = 4; o; o >>= 1)
            amax = fmaxf(amax, __shfl_xor_sync(0xffffffffu, amax, o));

        float s = fmaxf(amax, 1e-4f) / 448.0f;
        int e; float m = frexpf(s, &e);                // s = m*2^e, m in [0.5,1)
        float s2 = (m == 0.5f) ? ldexpf(1.f, e - 1) : ldexpf(1.f, e);
        float inv = 1.f / s2;                          // exact (power of two)

        uint32_t pk[4];
#pragma unroll
        for (int i = 0; i < 4; i++) {
            __nv_fp8x2_storage_t lo = __nv_cvt_float2_to_fp8x2(
                make_float2(v[4 * i + 0] * inv, v[4 * i + 1] * inv),
                __NV_SATFINITE, __NV_E4M3);
            __nv_fp8x2_storage_t hi = __nv_cvt_float2_to_fp8x2(
                make_float2(v[4 * i + 2] * inv, v[4 * i + 3] * inv),
                __NV_SATFINITE, __NV_E4M3);
            pk[i] = (uint32_t)lo | ((uint32_t)hi << 16);
        }
        *(uint4*)(g_x8 + b * 128 + r * 16) = make_uint4(pk[0], pk[1], pk[2], pk[3]);
        if (r == 0) g_sa[b] = s2;
    } else {
        // w: thread t handles 4 consecutive float4 -> one 16B fp8 store
        const size_t t = (size_t)(cta - XCTAS) * 256 + threadIdx.x;   // 0..262143
        const float4* pw = (const float4*)w + t * 4;
        uint32_t pk[4];
#pragma unroll
        for (int i = 0; i < 4; i++) {
            float4 w4 = pw[i];
            __nv_fp8x2_storage_t lo = __nv_cvt_float2_to_fp8x2(
                make_float2(w4.x, w4.y), __NV_SATFINITE, __NV_E4M3);
            __nv_fp8x2_storage_t hi = __nv_cvt_float2_to_fp8x2(
                make_float2(w4.z, w4.w), __NV_SATFINITE, __NV_E4M3);
            pk[i] = (uint32_t)lo | ((uint32_t)hi << 16);
        }
        *(uint4*)(g_w8 + t * 16) = make_uint4(pk[0], pk[1], pk[2], pk[3]);
    }
}

// ---------------------------------------------------------------------------
// FP8 NT GEMM (round-10 config verbatim — best measured, at the legacy
// mma.sync throughput floor of ~512 MAC/cyc/SM):
// CTA 64x64, 256 thr, 8 warps (4m x 2n), warp tile 16x32, regs<=80 ->
// 3 CTAs/SM. 4-stage cp.async ring, one __syncthreads per k-block,
// ldmatrix.x4, two-level block-scale accumulation, hoisted addresses.
// ---------------------------------------------------------------------------
constexpr int BM = 64, BN = 64;
constexpr int STAGES = 4;
constexpr int ROWB = 128 + 16;                       // 144 B/row, conflict-free
constexpr int STAGE_BYTES = (BM + BN) * ROWB;        // 18432
constexpr int SMEM_TOTAL = STAGES * STAGE_BYTES;     // 73728

__device__ __forceinline__ void cp_async16(uint32_t dst, const void* src) {
    asm volatile("cp.async.cg.shared.global [%0], [%1], 16;\n" :: "r"(dst), "l"(src));
}
__device__ __forceinline__ void cp_commit() {
    asm volatile("cp.async.commit_group;\n" ::: "memory");
}
template <int N>
__device__ __forceinline__ void cp_wait() {
    asm volatile("cp.async.wait_group %0;\n" :: "n"(N) : "memory");
}
__device__ __forceinline__ void ldm_x4(uint32_t& r0, uint32_t& r1, uint32_t& r2, uint32_t& r3,
                                       uint32_t addr) {
    asm volatile("ldmatrix.sync.aligned.m8n8.x4.shared.b16 {%0,%1,%2,%3}, [%4];\n"
                 : "=r"(r0), "=r"(r1), "=r"(r2), "=r"(r3) : "r"(addr));
}
__device__ __forceinline__ void mma_fp8(float* c, const uint32_t* a, const uint32_t* b) {
    asm volatile("mma.sync.aligned.m16n8k32.row.col.f32.e4m3.e4m3.f32 "
                 "{%0,%1,%2,%3}, {%4,%5,%6,%7}, {%8,%9}, {%0,%1,%2,%3};\n"
                 : "+f"(c[0]), "+f"(c[1]), "+f"(c[2]), "+f"(c[3])
                 : "r"(a[0]), "r"(a[1]), "r"(a[2]), "r"(a[3]), "r"(b[0]), "r"(b[1]));
}

__global__ __launch_bounds__(256, 3) void gemm_kernel(float* __restrict__ C,
                                                      const float* __restrict__ sinv) {
    extern __shared__ uint8_t sm[];
    const int tid = threadIdx.x;
    const int lane = tid & 31;
    const int wid = tid >> 5;                 // 0..7
    const int bm = blockIdx.y * BM;
    const int bn = blockIdx.x * BN;
    const int wm = (wid & 3) * 16;            // 4 m-tiles of 16
    const int wn = (wid >> 2) * 32;           // 2 n-cols of 32

    const uint32_t sm_u32 = (uint32_t)__cvta_generic_to_shared(sm);

    // ---- per-thread loader pointers: 1024 chunks of 16B, 4 per thread ----
    const uint8_t* gsrc[4];
    uint32_t soff[4];
#pragma unroll
    for (int i = 0; i < 4; i++) {
        int c = tid + 256 * i;                // 0..1023
        if (c < BM * 8) {                     // A chunk
            int row = c >> 3, cc = c & 7;
            gsrc[i] = g_x8 + (size_t)(bm + row) * KDIM + cc * 16;
            soff[i] = (uint32_t)(row * ROWB + cc * 16);
        } else {                              // B chunk
            int cb = c - BM * 8;
            int row = cb >> 3, cc = cb & 7;
            gsrc[i] = g_w8 + (size_t)(bn + row) * KDIM + cc * 16;
            soff[i] = (uint32_t)(BM * ROWB + row * ROWB + cc * 16);
        }
    }
    auto load_stage = [&](int s, int kb) {
        uint32_t base = sm_u32 + (uint32_t)(s * STAGE_BYTES);
        uint32_t koff = (uint32_t)kb << 7;    // kb * 128 bytes
#pragma unroll
        for (int i = 0; i < 4; i++)
            cp_async16(base + soff[i], gsrc[i] + koff);
    };

    float master[4][4];
#pragma unroll
    for (int j = 0; j < 4; j++)
#pragma unroll
        for (int l = 0; l < 4; l++) master[j][l] = 0.f;

    load_stage(0, 0); cp_commit();
    load_stage(1, 1); cp_commit();
    load_stage(2, 2); cp_commit();

    // hoisted ldmatrix address components
    const int la_row  = lane & 15;
    const int la_half = lane >> 4;
    const int lb_row  = ((lane >> 4) << 3) + (lane & 7);
    const int lb_half = (lane >> 3) & 1;
    const uint32_t aBase = (uint32_t)((wm + la_row) * ROWB + la_half * 16);
    const uint32_t bBase0 = (uint32_t)(BM * ROWB + (wn + lb_row) * ROWB + lb_half * 16);
    const uint32_t bBase1 = bBase0 + 16u * ROWB;
    const int gr = lane >> 2;

    // scale pointers (hoisted)
    const float* psa0 = g_sa + (size_t)(bm + wm + gr) * KB;   // rows c0,c1
    const float* psa1 = psa0 + 8 * KB;                        // rows c2,c3
    const float* psw  = sinv + (size_t)(bn >> 7) * KB;

    for (int kb = 0; kb < KB; kb++) {
        int rem = KB - 1 - kb;
        if (rem >= 2)      cp_wait<2>();
        else if (rem == 1) cp_wait<1>();
        else               cp_wait<0>();
        __syncthreads();
        if (kb + 3 < KB) { load_stage((kb + 3) & 3, kb + 3); cp_commit(); }

        const uint32_t st = sm_u32 + (uint32_t)((kb & 3) * STAGE_BYTES);

        float part[4][4];
#pragma unroll
        for (int j = 0; j < 4; j++)
#pragma unroll
            for (int l = 0; l < 4; l++) part[j][l] = 0.f;

#pragma unroll
        for (int ks = 0; ks < 4; ks++) {      // four k32 steps in BK=128
            const uint32_t k0 = (uint32_t)(ks * 32);
            uint32_t a[4];
            ldm_x4(a[0], a[1], a[2], a[3], st + aBase + k0);
#pragma unroll
            for (int p = 0; p < 2; p++) {
                uint32_t b[4];
                ldm_x4(b[0], b[1], b[2], b[3],
                       st + (p ? bBase1 : bBase0) + k0);
                mma_fp8(part[2 * p + 0], a, b + 0);
                mma_fp8(part[2 * p + 1], a, b + 2);
            }
        }

        // ---- fold k-block scales into master ----
        float swk = __ldg(psw + kb);
        float f0 = __ldg(psa0 + kb) * swk;    // acc rows c0,c1
        float f1 = __ldg(psa1 + kb) * swk;    // acc rows c2,c3
#pragma unroll
        for (int nt = 0; nt < 4; nt++) {
            master[nt][0] += part[nt][0] * f0;
            master[nt][1] += part[nt][1] * f0;
            master[nt][2] += part[nt][2] * f1;
            master[nt][3] += part[nt][3] * f1;
        }
    }

    // ---- epilogue: round to bf16, store as fp32 (float2) ----
    const int gid = lane >> 2, tig = lane & 3;
#pragma unroll
    for (int nt = 0; nt < 4; nt++) {
        int row = bm + wm + gid;
        int col = bn + wn + nt * 8 + tig * 2;
        float2 v01 = make_float2(bf16_round(master[nt][0]), bf16_round(master[nt][1]));
        *(float2*)&C[(size_t)row * NDIM + col] = v01;
        float2 v23 = make_float2(bf16_round(master[nt][2]), bf16_round(master[nt][3]));
        *(float2*)&C[(size_t)(row + 8) * NDIM + col] = v23;
    }
}

// ---------------------------------------------------------------------------
// Inputs identified BY ELEMENT COUNT: x 33554432, weight 4194304, sinv 256.
// ---------------------------------------------------------------------------
extern "C" void kernel_launch(void* const* d_in, const int* in_sizes, int n_in,
                              void* d_out, int out_size) {
    const float* x = nullptr; const float* w = nullptr; const float* sinv = nullptr;
    for (int i = 0; i < n_in; i++) {
        long long sz = in_sizes[i];
        if (sz == (long long)MDIM * KDIM)      x    = (const float*)d_in[i];
        else if (sz == (long long)NDIM * KDIM) w    = (const float*)d_in[i];
        else                                   sinv = (const float*)d_in[i];
    }
    if (!x)    x    = (const float*)d_in[0];
    if (!w)    w    = (const float*)d_in[1];
    if (!sinv) sinv = (const float*)d_in[2];
    float* out = (float*)d_out;

    // 1) fused quantization (x + w in one launch), v2 layout
    quant_fused_kernel<<<XCTAS + WCTAS, 256>>>(x, w);

    // 2) fp8 GEMM with per-block rescale (round-10 best-measured config)
    cudaFuncSetAttribute(gemm_kernel, cudaFuncAttributeMaxDynamicSharedMemorySize, SMEM_TOTAL);
    dim3 grid(NDIM / BN, MDIM / BM);               // (32, 256)
    gemm_kernel<<<grid, 256, SMEM_TOTAL>>>(out, sinv);
}